// round 1
// baseline (speedup 1.0000x reference)
#include <cuda_runtime.h>

// ROI-Align: img (8,64,64,1024) f32 NHWC, rois (32,4) int32 [x,y,w,h]
// out flat layout: [r][b][py][px][c]  (r-major), 32*8*7*7*1024 floats.
// One CTA per output bin (r,b,py,px); 256 threads x float4 = 1024 channels.

#define POOL 7
#define B 8
#define R 32
#define C 1024
#define W 64

__global__ void __launch_bounds__(256, 8)
roi_align_kernel(const float* __restrict__ img,
                 const int*   __restrict__ rois,
                 float*       __restrict__ out)
{
    int idx = blockIdx.x;
    const int px = idx % POOL; idx /= POOL;
    const int py = idx % POOL; idx /= POOL;
    const int b  = idx % B;    idx /= B;
    const int r  = idx;

    const int rx = rois[r * 4 + 0];
    const int ry = rois[r * 4 + 1];
    const int rw = rois[r * 4 + 2];
    const int rh = rois[r * 4 + 3];

    // coord = (p + 0.5) * (size/POOL) - 0.5   (matches reference fp32 order)
    const float sx = (float)rw / (float)POOL;
    const float sy = (float)rh / (float)POOL;

    const float cx = ((float)px + 0.5f) * sx - 0.5f;
    const float fx = floorf(cx);
    int x0 = (int)fx;            if (x0 < 0) x0 = 0;
    int x1 = (int)ceilf(cx);     if (x1 > rw - 1) x1 = rw - 1; if (x1 < 0) x1 = 0;
    const float wx = cx - fx;

    const float cy = ((float)py + 0.5f) * sy - 0.5f;
    const float fy = floorf(cy);
    int y0 = (int)fy;            if (y0 < 0) y0 = 0;
    int y1 = (int)ceilf(cy);     if (y1 > rh - 1) y1 = rh - 1; if (y1 < 0) y1 = 0;
    const float wy = cy - fy;

    x0 += rx; x1 += rx; y0 += ry; y1 += ry;

    const size_t base_b = (size_t)b * (W * W * C);
    const float4* __restrict__ p00 = (const float4*)(img + base_b + ((size_t)y0 * W + x0) * C);
    const float4* __restrict__ p01 = (const float4*)(img + base_b + ((size_t)y0 * W + x1) * C);
    const float4* __restrict__ p10 = (const float4*)(img + base_b + ((size_t)y1 * W + x0) * C);
    const float4* __restrict__ p11 = (const float4*)(img + base_b + ((size_t)y1 * W + x1) * C);

    const int t = threadIdx.x;  // 0..255, each covers 4 channels

    float4 v00 = __ldg(p00 + t);
    float4 v01 = __ldg(p01 + t);
    float4 v10 = __ldg(p10 + t);
    float4 v11 = __ldg(p11 + t);

    float4 res;
    {
        float top, bot;
        top = v00.x + (v01.x - v00.x) * wx;
        bot = v10.x + (v11.x - v10.x) * wx;
        res.x = top + (bot - top) * wy;
        top = v00.y + (v01.y - v00.y) * wx;
        bot = v10.y + (v11.y - v10.y) * wx;
        res.y = top + (bot - top) * wy;
        top = v00.z + (v01.z - v00.z) * wx;
        bot = v10.z + (v11.z - v10.z) * wx;
        res.z = top + (bot - top) * wy;
        top = v00.w + (v01.w - v00.w) * wx;
        bot = v10.w + (v11.w - v10.w) * wx;
        res.w = top + (bot - top) * wy;
    }

    float4* __restrict__ o = (float4*)(out + (size_t)blockIdx.x * C);
    o[t] = res;
}

extern "C" void kernel_launch(void* const* d_in, const int* in_sizes, int n_in,
                              void* d_out, int out_size)
{
    const float* img  = (const float*)d_in[0];
    const int*   rois = (const int*)d_in[1];
    float*       out  = (float*)d_out;

    const int nblocks = R * B * POOL * POOL;  // 12544
    roi_align_kernel<<<nblocks, 256>>>(img, rois, out);
}

// round 3
// speedup vs baseline: 1.1393x; 1.1393x over previous
#include <cuda_runtime.h>

// ROI-Align: img (8,64,64,1024) f32 NHWC, rois (32,4) int32 [x,y,w,h]
// out flat layout: [r][b][py][px][c]  (r-major), 32*8*7*7*1024 floats.
// Grid launched b-major (batch outermost) for wave-level L2 locality;
// output offset computed explicitly in r-major order.
// 128 threads/CTA, 8 channels per thread via 32-byte (v4.b64) loads with
// L2 evict_last hint; streaming (.cs) 16B output stores.

#define POOL 7
#define B 8
#define R 32
#define C 1024
#define W 64

struct F8 { float f[8]; };

__device__ __forceinline__ F8 ldg_el_32B(const void* p) {
    unsigned long long a, b, c, d;
    asm volatile("ld.global.nc.L2::evict_last.v4.b64 {%0,%1,%2,%3}, [%4];"
                 : "=l"(a), "=l"(b), "=l"(c), "=l"(d) : "l"(p));
    F8 r;
    r.f[0] = __uint_as_float((unsigned)(a      )); r.f[1] = __uint_as_float((unsigned)(a >> 32));
    r.f[2] = __uint_as_float((unsigned)(b      )); r.f[3] = __uint_as_float((unsigned)(b >> 32));
    r.f[4] = __uint_as_float((unsigned)(c      )); r.f[5] = __uint_as_float((unsigned)(c >> 32));
    r.f[6] = __uint_as_float((unsigned)(d      )); r.f[7] = __uint_as_float((unsigned)(d >> 32));
    return r;
}

__device__ __forceinline__ void stg_cs(float* p, float x, float y, float z, float w) {
    asm volatile("st.global.cs.v4.f32 [%0], {%1,%2,%3,%4};"
                 :: "l"(p), "f"(x), "f"(y), "f"(z), "f"(w) : "memory");
}

__global__ void __launch_bounds__(128, 16)
roi_align_kernel(const float* __restrict__ img,
                 const int*   __restrict__ rois,
                 float*       __restrict__ out)
{
    // grid order: (((b*R + r)*POOL + py)*POOL + px)   -- b outermost
    int idx = blockIdx.x;
    const int px = idx % POOL; idx /= POOL;
    const int py = idx % POOL; idx /= POOL;
    const int r  = idx % R;    idx /= R;
    const int b  = idx;

    const int rx = rois[r * 4 + 0];
    const int ry = rois[r * 4 + 1];
    const int rw = rois[r * 4 + 2];
    const int rh = rois[r * 4 + 3];

    // coord = (p + 0.5) * (size/POOL) - 0.5   (matches reference fp32 order)
    const float sx = (float)rw / (float)POOL;
    const float sy = (float)rh / (float)POOL;

    const float cx = ((float)px + 0.5f) * sx - 0.5f;
    const float fx = floorf(cx);
    int x0 = (int)fx;            if (x0 < 0) x0 = 0;
    int x1 = (int)ceilf(cx);     if (x1 > rw - 1) x1 = rw - 1; if (x1 < 0) x1 = 0;
    const float wx = cx - fx;

    const float cy = ((float)py + 0.5f) * sy - 0.5f;
    const float fy = floorf(cy);
    int y0 = (int)fy;            if (y0 < 0) y0 = 0;
    int y1 = (int)ceilf(cy);     if (y1 > rh - 1) y1 = rh - 1; if (y1 < 0) y1 = 0;
    const float wy = cy - fy;

    const int gx0 = x0 + rx, gx1 = x1 + rx, gy0 = y0 + ry, gy1 = y1 + ry;

    const size_t base_b = (size_t)b * (W * W * C);
    const int t = threadIdx.x;            // 0..127
    const size_t coff = (size_t)t * 8;    // 8 channels per thread

    const float* p00 = img + base_b + ((size_t)gy0 * W + gx0) * C + coff;
    const float* p01 = img + base_b + ((size_t)gy0 * W + gx1) * C + coff;
    const float* p10 = img + base_b + ((size_t)gy1 * W + gx0) * C + coff;
    const float* p11 = img + base_b + ((size_t)gy1 * W + gx1) * C + coff;

    F8 v00 = ldg_el_32B(p00);
    F8 v01 = ldg_el_32B(p01);
    F8 v10 = ldg_el_32B(p10);
    F8 v11 = ldg_el_32B(p11);

    float res[8];
#pragma unroll
    for (int i = 0; i < 8; i++) {
        float top = v00.f[i] + (v01.f[i] - v00.f[i]) * wx;
        float bot = v10.f[i] + (v11.f[i] - v10.f[i]) * wx;
        res[i] = top + (bot - top) * wy;
    }

    // output offset: r-major layout [r][b][py][px][c]
    const size_t obin = ((((size_t)r * B + b) * POOL + py) * POOL + px) * C;
    float* o = out + obin + coff;
    stg_cs(o,     res[0], res[1], res[2], res[3]);
    stg_cs(o + 4, res[4], res[5], res[6], res[7]);
}

extern "C" void kernel_launch(void* const* d_in, const int* in_sizes, int n_in,
                              void* d_out, int out_size)
{
    const float* img  = (const float*)d_in[0];
    const int*   rois = (const int*)d_in[1];
    float*       out  = (float*)d_out;

    const int nblocks = R * B * POOL * POOL;  // 12544
    roi_align_kernel<<<nblocks, 128>>>(img, rois, out);
}